// round 1
// baseline (speedup 1.0000x reference)
#include <cuda_runtime.h>

#define NN 512

// Scratch (device globals — no allocation allowed)
__device__ float g_H1[NN * NN];
__device__ float g_H2[NN * NN];
__device__ float g_G1[NN * NN];
__device__ float g_G2[NN * NN];

constexpr int BM = 32;   // rows per tile
constexpr int BN = 64;   // cols per tile
constexpr int BK = 16;   // k per tile
// 256 threads: tx in [0,16), ty in [0,16); each thread computes 2x4 outputs.

// ---------------------------------------------------------------------------
// Kernel 1: H1 = relu(X @ W1 + b1)
// ---------------------------------------------------------------------------
__global__ void k_h1(const float* __restrict__ X, const float* __restrict__ W1,
                     const float* __restrict__ b1) {
    __shared__ float As[BK][BM + 1];  // transposed: As[k][m]
    __shared__ float Bs[BK][BN];      // natural:   Bs[k][n]
    const int t  = threadIdx.x;
    const int tx = t & 15, ty = t >> 4;
    const int rowBase = blockIdx.y * BM;
    const int colBase = blockIdx.x * BN;

    float acc[2][4] = {};
    for (int k0 = 0; k0 < NN; k0 += BK) {
        if (t < 128) {
            int r = t >> 2, c = (t & 3) << 2;
            float4 v = *(const float4*)(X + (rowBase + r) * NN + k0 + c);
            As[c + 0][r] = v.x; As[c + 1][r] = v.y;
            As[c + 2][r] = v.z; As[c + 3][r] = v.w;
        }
        {
            int r = t >> 4, c = (t & 15) << 2;
            float4 v = *(const float4*)(W1 + (k0 + r) * NN + colBase + c);
            Bs[r][c + 0] = v.x; Bs[r][c + 1] = v.y;
            Bs[r][c + 2] = v.z; Bs[r][c + 3] = v.w;
        }
        __syncthreads();
#pragma unroll
        for (int kk = 0; kk < BK; ++kk) {
            float a0 = As[kk][ty * 2 + 0];
            float a1 = As[kk][ty * 2 + 1];
            float b[4];
#pragma unroll
            for (int j = 0; j < 4; ++j) b[j] = Bs[kk][tx * 4 + j];
#pragma unroll
            for (int j = 0; j < 4; ++j) {
                acc[0][j] += a0 * b[j];
                acc[1][j] += a1 * b[j];
            }
        }
        __syncthreads();
    }
#pragma unroll
    for (int i = 0; i < 2; ++i)
#pragma unroll
        for (int j = 0; j < 4; ++j) {
            int row = rowBase + ty * 2 + i;
            int col = colBase + tx * 4 + j;
            float z = acc[i][j] + b1[col];
            g_H1[row * NN + col] = fmaxf(z, 0.f);
        }
}

// ---------------------------------------------------------------------------
// Kernel 2: Z2 = H1 @ W2 + b2 ; H2 = relu(Z2) ; G2 = w3 * (Z2 > 0)
// ---------------------------------------------------------------------------
__global__ void k_h2g2(const float* __restrict__ W2, const float* __restrict__ b2,
                       const float* __restrict__ w3) {
    __shared__ float As[BK][BM + 1];
    __shared__ float Bs[BK][BN];
    const int t  = threadIdx.x;
    const int tx = t & 15, ty = t >> 4;
    const int rowBase = blockIdx.y * BM;
    const int colBase = blockIdx.x * BN;

    float acc[2][4] = {};
    for (int k0 = 0; k0 < NN; k0 += BK) {
        if (t < 128) {
            int r = t >> 2, c = (t & 3) << 2;
            float4 v = *(const float4*)(g_H1 + (rowBase + r) * NN + k0 + c);
            As[c + 0][r] = v.x; As[c + 1][r] = v.y;
            As[c + 2][r] = v.z; As[c + 3][r] = v.w;
        }
        {
            int r = t >> 4, c = (t & 15) << 2;
            float4 v = *(const float4*)(W2 + (k0 + r) * NN + colBase + c);
            Bs[r][c + 0] = v.x; Bs[r][c + 1] = v.y;
            Bs[r][c + 2] = v.z; Bs[r][c + 3] = v.w;
        }
        __syncthreads();
#pragma unroll
        for (int kk = 0; kk < BK; ++kk) {
            float a0 = As[kk][ty * 2 + 0];
            float a1 = As[kk][ty * 2 + 1];
            float b[4];
#pragma unroll
            for (int j = 0; j < 4; ++j) b[j] = Bs[kk][tx * 4 + j];
#pragma unroll
            for (int j = 0; j < 4; ++j) {
                acc[0][j] += a0 * b[j];
                acc[1][j] += a1 * b[j];
            }
        }
        __syncthreads();
    }
#pragma unroll
    for (int i = 0; i < 2; ++i)
#pragma unroll
        for (int j = 0; j < 4; ++j) {
            int row = rowBase + ty * 2 + i;
            int col = colBase + tx * 4 + j;
            float z = acc[i][j] + b2[col];
            g_H2[row * NN + col] = fmaxf(z, 0.f);
            g_G2[row * NN + col] = (z > 0.f) ? w3[col] : 0.f;
        }
}

// ---------------------------------------------------------------------------
// Kernel 3: T = G2 @ W2^T ; G1 = T * (H1 > 0)
//   T[i][n] = sum_j G2[i][j] * W2[n][j]
// ---------------------------------------------------------------------------
__global__ void k_g1(const float* __restrict__ W2) {
    __shared__ float As[BK][BM + 1];
    __shared__ float Bs[BK][BN + 1];  // transposed store: Bs[j][n]
    const int t  = threadIdx.x;
    const int tx = t & 15, ty = t >> 4;
    const int rowBase = blockIdx.y * BM;
    const int colBase = blockIdx.x * BN;

    float acc[2][4] = {};
    for (int k0 = 0; k0 < NN; k0 += BK) {
        if (t < 128) {
            int r = t >> 2, c = (t & 3) << 2;
            float4 v = *(const float4*)(g_G2 + (rowBase + r) * NN + k0 + c);
            As[c + 0][r] = v.x; As[c + 1][r] = v.y;
            As[c + 2][r] = v.z; As[c + 3][r] = v.w;
        }
        {
            // 64 rows (n) x 16 cols (j): r = t/4 in [0,64), c = (t%4)*4
            int r = t >> 2, c = (t & 3) << 2;
            float4 v = *(const float4*)(W2 + (colBase + r) * NN + k0 + c);
            Bs[c + 0][r] = v.x; Bs[c + 1][r] = v.y;
            Bs[c + 2][r] = v.z; Bs[c + 3][r] = v.w;
        }
        __syncthreads();
#pragma unroll
        for (int kk = 0; kk < BK; ++kk) {
            float a0 = As[kk][ty * 2 + 0];
            float a1 = As[kk][ty * 2 + 1];
            float b[4];
#pragma unroll
            for (int j = 0; j < 4; ++j) b[j] = Bs[kk][tx * 4 + j];
#pragma unroll
            for (int j = 0; j < 4; ++j) {
                acc[0][j] += a0 * b[j];
                acc[1][j] += a1 * b[j];
            }
        }
        __syncthreads();
    }
#pragma unroll
    for (int i = 0; i < 2; ++i)
#pragma unroll
        for (int j = 0; j < 4; ++j) {
            int row = rowBase + ty * 2 + i;
            int col = colBase + tx * 4 + j;
            float mask = (g_H1[row * NN + col] > 0.f) ? 1.f : 0.f;
            g_G1[row * NN + col] = acc[i][j] * mask;
        }
}

// ---------------------------------------------------------------------------
// Kernel 4: output[i] = H2[i,:] . w3 + b3[0]
// ---------------------------------------------------------------------------
__global__ void k_out(const float* __restrict__ w3, const float* __restrict__ b3,
                      float* __restrict__ out) {
    const int row = blockIdx.x;
    const int t = threadIdx.x;
    float s = 0.f;
    for (int j = t; j < NN; j += 128) s += g_H2[row * NN + j] * w3[j];
#pragma unroll
    for (int o = 16; o > 0; o >>= 1) s += __shfl_down_sync(0xffffffffu, s, o);
    __shared__ float red[4];
    if ((t & 31) == 0) red[t >> 5] = s;
    __syncthreads();
    if (t == 0) out[row] = red[0] + red[1] + red[2] + red[3] + b3[0];
}

// ---------------------------------------------------------------------------
// Kernel 5: fused 5-way Gram products + combine
//   Gram[i][j] = 1 + <h2_i,h2_j> + <g2_i,g2_j>(1+<h1_i,h1_j>)
//                  + <g1_i,g1_j>(1+<x_i,x_j>)
// ---------------------------------------------------------------------------
__global__ void k_gram(const float* __restrict__ X, float* __restrict__ gram) {
    __shared__ float Rs[5][BK][BM + 1];  // row tiles (transposed)
    __shared__ float Cs[5][BK][BN + 1];  // col tiles (transposed)
    const int t  = threadIdx.x;
    const int tx = t & 15, ty = t >> 4;
    const int rowBase = blockIdx.y * BM;
    const int colBase = blockIdx.x * BN;

    const float* mats[5] = {X, g_H1, g_H2, g_G1, g_G2};

    float acc[5][2][4] = {};
    for (int k0 = 0; k0 < NN; k0 += BK) {
#pragma unroll
        for (int m = 0; m < 5; ++m) {
            if (t < 128) {
                int r = t >> 2, c = (t & 3) << 2;
                float4 v = *(const float4*)(mats[m] + (rowBase + r) * NN + k0 + c);
                Rs[m][c + 0][r] = v.x; Rs[m][c + 1][r] = v.y;
                Rs[m][c + 2][r] = v.z; Rs[m][c + 3][r] = v.w;
            }
            {
                int r = t >> 2, c = (t & 3) << 2;  // 64 rows x 16 k
                float4 v = *(const float4*)(mats[m] + (colBase + r) * NN + k0 + c);
                Cs[m][c + 0][r] = v.x; Cs[m][c + 1][r] = v.y;
                Cs[m][c + 2][r] = v.z; Cs[m][c + 3][r] = v.w;
            }
        }
        __syncthreads();
#pragma unroll
        for (int kk = 0; kk < BK; ++kk) {
#pragma unroll
            for (int m = 0; m < 5; ++m) {
                float a0 = Rs[m][kk][ty * 2 + 0];
                float a1 = Rs[m][kk][ty * 2 + 1];
                float b[4];
#pragma unroll
                for (int j = 0; j < 4; ++j) b[j] = Cs[m][kk][tx * 4 + j];
#pragma unroll
                for (int j = 0; j < 4; ++j) {
                    acc[m][0][j] += a0 * b[j];
                    acc[m][1][j] += a1 * b[j];
                }
            }
        }
        __syncthreads();
    }

#pragma unroll
    for (int i = 0; i < 2; ++i)
#pragma unroll
        for (int j = 0; j < 4; ++j) {
            int row = rowBase + ty * 2 + i;
            int col = colBase + tx * 4 + j;
            float sX  = acc[0][i][j];
            float sH1 = acc[1][i][j];
            float sH2 = acc[2][i][j];
            float sG1 = acc[3][i][j];
            float sG2 = acc[4][i][j];
            float g = 1.f + sH2 + sG2 * (1.f + sH1) + sG1 * (1.f + sX);
            gram[row * NN + col] = g;
        }
}

// ---------------------------------------------------------------------------
// Launch
// ---------------------------------------------------------------------------
extern "C" void kernel_launch(void* const* d_in, const int* in_sizes, int n_in,
                              void* d_out, int out_size) {
    const float* x  = (const float*)d_in[0];
    const float* W1 = (const float*)d_in[1];
    const float* b1 = (const float*)d_in[2];
    const float* W2 = (const float*)d_in[3];
    const float* b2 = (const float*)d_in[4];
    const float* w3 = (const float*)d_in[5];
    const float* b3 = (const float*)d_in[6];

    float* out  = (float*)d_out;         // [512] per-sample outputs
    float* gram = (float*)d_out + NN;    // [512 x 512] gramian

    dim3 grid(NN / BN, NN / BM);  // (8, 16) = 128 blocks
    dim3 block(256);

    k_h1<<<grid, block>>>(x, W1, b1);
    k_h2g2<<<grid, block>>>(W2, b2, w3);
    k_g1<<<grid, block>>>(W2);
    k_out<<<NN, 128>>>(w3, b3, out);
    k_gram<<<grid, block>>>(x, gram);
}

// round 2
// speedup vs baseline: 2.1119x; 2.1119x over previous
#include <cuda_runtime.h>

#define NN 512

// Scratch (device globals — no allocation allowed)
__device__ float g_H1[NN * NN];
__device__ float g_H2[NN * NN];
__device__ float g_G1[NN * NN];
__device__ float g_G2[NN * NN];
// Per-matrix gram partial sums (only lower-triangle blocks are valid)
__device__ float g_PX [NN * NN];
__device__ float g_PH1[NN * NN];
__device__ float g_PH2[NN * NN];
__device__ float g_PG1[NN * NN];
__device__ float g_PG2[NN * NN];

constexpr int BK = 16;
constexpr int BMt = 32;   // tile rows
constexpr int BNt = 64;   // tile cols
constexpr int AS_STRIDE = 36;  // padded row stride (floats), 16B-aligned
constexpr int BS_STRIDE = 68;  // padded row stride (floats), 16B-aligned
// 128 threads: tx in [0,16) cols, ty in [0,8) rows; each thread computes 4x4.

// ---------------------------------------------------------------------------
// Tiled GEMM mainloop. BTrans=false: C = A @ B   (B row-major [K,N])
//                      BTrans=true : C = A @ B^T (B row-major [N,K])
// Tile: 32 (rows) x 64 (cols), BK=16, 128 threads, 4x4 micro-tile.
// acc[i][j] corresponds to row rowBase + ty*4+i, col colBase + tx*4+j.
// ---------------------------------------------------------------------------
template <bool BTrans>
__device__ __forceinline__ void gemm_tile(const float* __restrict__ A,
                                          const float* __restrict__ B,
                                          int rowBase, int colBase,
                                          float acc[4][4]) {
    __shared__ float As[BK * AS_STRIDE];
    __shared__ float Bs[BK * BS_STRIDE];
    const int t = threadIdx.x;
    const int tx = t & 15, ty = t >> 4;

    // A load mapping: 32x16 tile = 128 float4, 1 per thread
    const int ar = t >> 2;            // row 0..31
    const int ac = (t & 3) << 2;      // k offset 0,4,8,12
    // B load mapping: 16x64 (or 64x16) = 256 float4, 2 per thread
    // natural: idx -> r=idx>>4 (k row 0..15), c=(idx&15)<<2 (col)
    // trans:   idx -> r=idx>>2 (n row 0..63), c=(idx&3)<<2 (k)
    const int i0 = t, i1 = t + 128;

    float4 fa, fb0, fb1;

    auto loadAll = [&](int k0) {
        fa = *(const float4*)(A + (rowBase + ar) * NN + k0 + ac);
        if (BTrans) {
            int r0 = i0 >> 2, c0 = (i0 & 3) << 2;
            int r1 = i1 >> 2, c1 = (i1 & 3) << 2;
            fb0 = *(const float4*)(B + (colBase + r0) * NN + k0 + c0);
            fb1 = *(const float4*)(B + (colBase + r1) * NN + k0 + c1);
        } else {
            int r0 = i0 >> 4, c0 = (i0 & 15) << 2;
            int r1 = i1 >> 4, c1 = (i1 & 15) << 2;
            fb0 = *(const float4*)(B + (k0 + r0) * NN + colBase + c0);
            fb1 = *(const float4*)(B + (k0 + r1) * NN + colBase + c1);
        }
    };
    auto storeAll = [&]() {
        As[(ac + 0) * AS_STRIDE + ar] = fa.x;
        As[(ac + 1) * AS_STRIDE + ar] = fa.y;
        As[(ac + 2) * AS_STRIDE + ar] = fa.z;
        As[(ac + 3) * AS_STRIDE + ar] = fa.w;
        if (BTrans) {
            int r0 = i0 >> 2, c0 = (i0 & 3) << 2;
            int r1 = i1 >> 2, c1 = (i1 & 3) << 2;
            Bs[(c0 + 0) * BS_STRIDE + r0] = fb0.x;
            Bs[(c0 + 1) * BS_STRIDE + r0] = fb0.y;
            Bs[(c0 + 2) * BS_STRIDE + r0] = fb0.z;
            Bs[(c0 + 3) * BS_STRIDE + r0] = fb0.w;
            Bs[(c1 + 0) * BS_STRIDE + r1] = fb1.x;
            Bs[(c1 + 1) * BS_STRIDE + r1] = fb1.y;
            Bs[(c1 + 2) * BS_STRIDE + r1] = fb1.z;
            Bs[(c1 + 3) * BS_STRIDE + r1] = fb1.w;
        } else {
            int r0 = i0 >> 4, c0 = (i0 & 15) << 2;
            int r1 = i1 >> 4, c1 = (i1 & 15) << 2;
            *(float4*)&Bs[r0 * BS_STRIDE + c0] = fb0;
            *(float4*)&Bs[r1 * BS_STRIDE + c1] = fb1;
        }
    };

    loadAll(0);
    for (int k0 = 0; k0 < NN; k0 += BK) {
        storeAll();
        __syncthreads();
        if (k0 + BK < NN) loadAll(k0 + BK);
#pragma unroll
        for (int kk = 0; kk < BK; ++kk) {
            float4 a4 = *(const float4*)&As[kk * AS_STRIDE + ty * 4];
            float4 b4 = *(const float4*)&Bs[kk * BS_STRIDE + tx * 4];
            float av[4] = {a4.x, a4.y, a4.z, a4.w};
            float bv[4] = {b4.x, b4.y, b4.z, b4.w};
#pragma unroll
            for (int i = 0; i < 4; ++i)
#pragma unroll
                for (int j = 0; j < 4; ++j) acc[i][j] += av[i] * bv[j];
        }
        __syncthreads();
    }
}

// ---------------------------------------------------------------------------
// Kernel 1: H1 = relu(X @ W1 + b1)
// ---------------------------------------------------------------------------
__global__ void __launch_bounds__(128) k_h1(const float* __restrict__ X,
                                            const float* __restrict__ W1,
                                            const float* __restrict__ b1) {
    const int rowBase = blockIdx.y * BMt;
    const int colBase = blockIdx.x * BNt;
    const int tx = threadIdx.x & 15, ty = threadIdx.x >> 4;
    float acc[4][4] = {};
    gemm_tile<false>(X, W1, rowBase, colBase, acc);
#pragma unroll
    for (int i = 0; i < 4; ++i)
#pragma unroll
        for (int j = 0; j < 4; ++j) {
            int row = rowBase + ty * 4 + i;
            int col = colBase + tx * 4 + j;
            float z = acc[i][j] + b1[col];
            g_H1[row * NN + col] = fmaxf(z, 0.f);
        }
}

// ---------------------------------------------------------------------------
// Kernel 2: Z2 = H1 @ W2 + b2 ; H2 = relu(Z2) ; G2 = w3 * (Z2 > 0)
// ---------------------------------------------------------------------------
__global__ void __launch_bounds__(128) k_h2g2(const float* __restrict__ W2,
                                              const float* __restrict__ b2,
                                              const float* __restrict__ w3) {
    const int rowBase = blockIdx.y * BMt;
    const int colBase = blockIdx.x * BNt;
    const int tx = threadIdx.x & 15, ty = threadIdx.x >> 4;
    float acc[4][4] = {};
    gemm_tile<false>(g_H1, W2, rowBase, colBase, acc);
#pragma unroll
    for (int i = 0; i < 4; ++i)
#pragma unroll
        for (int j = 0; j < 4; ++j) {
            int row = rowBase + ty * 4 + i;
            int col = colBase + tx * 4 + j;
            float z = acc[i][j] + b2[col];
            g_H2[row * NN + col] = fmaxf(z, 0.f);
            g_G2[row * NN + col] = (z > 0.f) ? w3[col] : 0.f;
        }
}

// ---------------------------------------------------------------------------
// Kernel 3: T = G2 @ W2^T ; G1 = T * (H1 > 0)
// ---------------------------------------------------------------------------
__global__ void __launch_bounds__(128) k_g1(const float* __restrict__ W2) {
    const int rowBase = blockIdx.y * BMt;
    const int colBase = blockIdx.x * BNt;
    const int tx = threadIdx.x & 15, ty = threadIdx.x >> 4;
    float acc[4][4] = {};
    gemm_tile<true>(g_G2, W2, rowBase, colBase, acc);
#pragma unroll
    for (int i = 0; i < 4; ++i)
#pragma unroll
        for (int j = 0; j < 4; ++j) {
            int row = rowBase + ty * 4 + i;
            int col = colBase + tx * 4 + j;
            float mask = (g_H1[row * NN + col] > 0.f) ? 1.f : 0.f;
            g_G1[row * NN + col] = acc[i][j] * mask;
        }
}

// ---------------------------------------------------------------------------
// Kernel 4: output[i] = H2[i,:] . w3 + b3[0]   (one warp per row)
// ---------------------------------------------------------------------------
__global__ void __launch_bounds__(256) k_out(const float* __restrict__ w3,
                                             const float* __restrict__ b3,
                                             float* __restrict__ out) {
    const int w = threadIdx.x >> 5, lane = threadIdx.x & 31;
    const int row = blockIdx.x * 8 + w;
    const float4* h = (const float4*)(g_H2 + row * NN);
    const float4* wv = (const float4*)w3;
    float s = 0.f;
#pragma unroll
    for (int c = lane; c < NN / 4; c += 32) {
        float4 a = h[c], b = wv[c];
        s += a.x * b.x + a.y * b.y + a.z * b.z + a.w * b.w;
    }
#pragma unroll
    for (int o = 16; o > 0; o >>= 1) s += __shfl_xor_sync(0xffffffffu, s, o);
    if (lane == 0) out[row] = s + b3[0];
}

// ---------------------------------------------------------------------------
// Lower-triangle block mapping: 16 row-blocks (32) x 8 col-blocks (64).
// Block (by,bx) included iff 64*bx <= 32*by+31  -> count(by) = by/2 + 1.
// Total 72 blocks.
// ---------------------------------------------------------------------------
__device__ __forceinline__ void tri_map(int L, int& by, int& bx) {
    by = 0;
    while (L >= (by >> 1) + 1) {
        L -= (by >> 1) + 1;
        ++by;
    }
    bx = L;
}

// ---------------------------------------------------------------------------
// Kernel 5: per-matrix gram partials: P_m = M @ M^T, lower-triangle blocks.
// grid: (72, 5). blockIdx.y selects the matrix.
// ---------------------------------------------------------------------------
__global__ void __launch_bounds__(128) k_gram5(const float* __restrict__ X) {
    int by, bx;
    tri_map(blockIdx.x, by, bx);
    const int rowBase = by * BMt;
    const int colBase = bx * BNt;
    const int tx = threadIdx.x & 15, ty = threadIdx.x >> 4;

    const float* mat;
    float* part;
    switch (blockIdx.y) {
        case 0: mat = X;     part = g_PX;  break;
        case 1: mat = g_H1;  part = g_PH1; break;
        case 2: mat = g_H2;  part = g_PH2; break;
        case 3: mat = g_G1;  part = g_PG1; break;
        default: mat = g_G2; part = g_PG2; break;
    }

    float acc[4][4] = {};
    gemm_tile<true>(mat, mat, rowBase, colBase, acc);
#pragma unroll
    for (int i = 0; i < 4; ++i)
#pragma unroll
        for (int j = 0; j < 4; ++j) {
            int row = rowBase + ty * 4 + i;
            int col = colBase + tx * 4 + j;
            part[row * NN + col] = acc[i][j];
        }
}

// ---------------------------------------------------------------------------
// Kernel 6: combine partials + mirror.
//   Gram[i][j] = 1 + sH2 + sG2*(1+sH1) + sG1*(1+sX), symmetric.
// grid: 72 blocks of 256 threads; each handles a 32x64 block's i>=j entries.
// ---------------------------------------------------------------------------
__global__ void __launch_bounds__(256) k_combine(float* __restrict__ gram) {
    int by, bx;
    tri_map(blockIdx.x, by, bx);
    const int rowBase = by * BMt;
    const int colBase = bx * BNt;
    for (int idx = threadIdx.x; idx < BMt * BNt; idx += 256) {
        int r = idx >> 6, c = idx & 63;
        int i = rowBase + r, j = colBase + c;
        if (j > i) continue;
        int off = i * NN + j;
        float sX  = g_PX[off];
        float sH1 = g_PH1[off];
        float sH2 = g_PH2[off];
        float sG1 = g_PG1[off];
        float sG2 = g_PG2[off];
        float g = 1.f + sH2 + sG2 * (1.f + sH1) + sG1 * (1.f + sX);
        gram[off] = g;
        gram[j * NN + i] = g;
    }
}

// ---------------------------------------------------------------------------
// Launch
// ---------------------------------------------------------------------------
extern "C" void kernel_launch(void* const* d_in, const int* in_sizes, int n_in,
                              void* d_out, int out_size) {
    const float* x  = (const float*)d_in[0];
    const float* W1 = (const float*)d_in[1];
    const float* b1 = (const float*)d_in[2];
    const float* W2 = (const float*)d_in[3];
    const float* b2 = (const float*)d_in[4];
    const float* w3 = (const float*)d_in[5];
    const float* b3 = (const float*)d_in[6];

    float* out  = (float*)d_out;       // [512]
    float* gram = (float*)d_out + NN;  // [512 x 512]

    dim3 grid(NN / BNt, NN / BMt);     // (8, 16) = 128 blocks
    dim3 block(128);

    k_h1<<<grid, block>>>(x, W1, b1);
    k_h2g2<<<grid, block>>>(W2, b2, w3);
    k_g1<<<grid, block>>>(W2);
    k_out<<<NN / 8, 256>>>(w3, b3, out);
    k_gram5<<<dim3(72, 5), block>>>(x);
    k_combine<<<72, 256>>>(gram);
}

// round 4
// speedup vs baseline: 2.7890x; 1.3206x over previous
#include <cuda_runtime.h>
#include <cuda_bf16.h>
#include <cstdint>

#define NN 512
using bf16 = __nv_bfloat16;

// ---------------------------------------------------------------------------
// Device scratch (no allocation allowed)
// ---------------------------------------------------------------------------
#define DECLB(n) __device__ __align__(16) bf16 n[NN * NN]
DECLB(g_Xhi);   DECLB(g_Xlo);
DECLB(g_W1Thi); DECLB(g_W1Tlo);
DECLB(g_W2Thi); DECLB(g_W2Tlo);
DECLB(g_W2hi);  DECLB(g_W2lo);
DECLB(g_H1hi);  DECLB(g_H1lo);
DECLB(g_H2hi);  DECLB(g_H2lo);
DECLB(g_G1hi);  DECLB(g_G1lo);
DECLB(g_G2hi);  DECLB(g_G2lo);
__device__ __align__(16) float g_H2f[NN * NN];
__device__ __align__(16) float g_PX [NN * NN];
__device__ __align__(16) float g_PH1[NN * NN];
__device__ __align__(16) float g_PH2[NN * NN];
__device__ __align__(16) float g_PG1[NN * NN];
__device__ __align__(16) float g_PG2[NN * NN];

// ---------------------------------------------------------------------------
// PTX helpers (base-PTX only: ldmatrix + mma.sync, valid on target sm_103)
// ---------------------------------------------------------------------------
__device__ __forceinline__ uint32_t smem_u32(const void* p) {
    return (uint32_t)__cvta_generic_to_shared(p);
}

__device__ __forceinline__ void ldm_x4(uint32_t a[4], uint32_t addr) {
    asm volatile("ldmatrix.sync.aligned.m8n8.x4.shared.b16 {%0,%1,%2,%3}, [%4];"
                 : "=r"(a[0]), "=r"(a[1]), "=r"(a[2]), "=r"(a[3]) : "r"(addr));
}
__device__ __forceinline__ void ldm_x2(uint32_t b[2], uint32_t addr) {
    asm volatile("ldmatrix.sync.aligned.m8n8.x2.shared.b16 {%0,%1}, [%2];"
                 : "=r"(b[0]), "=r"(b[1]) : "r"(addr));
}
__device__ __forceinline__ void mma_bf16(float c[4], const uint32_t a[4],
                                         const uint32_t b[2]) {
    asm volatile(
        "mma.sync.aligned.m16n8k16.row.col.f32.bf16.bf16.f32 "
        "{%0,%1,%2,%3}, {%4,%5,%6,%7}, {%8,%9}, {%0,%1,%2,%3};"
        : "+f"(c[0]), "+f"(c[1]), "+f"(c[2]), "+f"(c[3])
        : "r"(a[0]), "r"(a[1]), "r"(a[2]), "r"(a[3]), "r"(b[0]), "r"(b[1]));
}

// ---------------------------------------------------------------------------
// Shared-memory staging: double-buffered, 2 k16 sub-slices per stage (k32).
// Row stride 24 halfs (48 B): conflict-free for ldmatrix row fetches.
// ---------------------------------------------------------------------------
struct __align__(16) Smem {
    bf16 Ahi[2][2][64][24];
    bf16 Alo[2][2][64][24];
    bf16 Bhi[2][2][32][24];
    bf16 Blo[2][2][32][24];
};

// CTA tile: M=64, N=32, 128 threads (4 warps as 2m x 2n, warp tile 32x16).
// acc[fm][fn][4] : m16n8 fragments.
__device__ __forceinline__ void mainloop(
    const bf16* __restrict__ Ahi, const bf16* __restrict__ Alo,
    const bf16* __restrict__ Bhi, const bf16* __restrict__ Blo,
    int rowBase, int colBase, Smem& s, float acc[2][2][4])
{
    const int t = threadIdx.x;
    const int lane = t & 31, wid = t >> 5;
    const int wm = wid & 1, wn = wid >> 1;

    // global-load / smem-store index precompute
    const int ar0 = t >> 2,        ach0 = t & 3;          // A task 0
    const int ar1 = (t + 128) >> 2, ach1 = (t + 128) & 3; // A task 1
    const int br = t >> 2,         bch = t & 3;           // B task

    uint4 ra0h, ra0l, ra1h, ra1l, rbh, rbl;

    auto gload = [&](int st) {
        const int k0 = st * 32;
        ra0h = *(const uint4*)(Ahi + (rowBase + ar0) * NN + k0 + ach0 * 8);
        ra0l = *(const uint4*)(Alo + (rowBase + ar0) * NN + k0 + ach0 * 8);
        ra1h = *(const uint4*)(Ahi + (rowBase + ar1) * NN + k0 + ach1 * 8);
        ra1l = *(const uint4*)(Alo + (rowBase + ar1) * NN + k0 + ach1 * 8);
        rbh  = *(const uint4*)(Bhi + (colBase + br) * NN + k0 + bch * 8);
        rbl  = *(const uint4*)(Blo + (colBase + br) * NN + k0 + bch * 8);
    };
    auto sstore = [&](int buf) {
        {
            int sub = ach0 >> 1, o = (ach0 & 1) * 8;
            *(uint4*)&s.Ahi[buf][sub][ar0][o] = ra0h;
            *(uint4*)&s.Alo[buf][sub][ar0][o] = ra0l;
        }
        {
            int sub = ach1 >> 1, o = (ach1 & 1) * 8;
            *(uint4*)&s.Ahi[buf][sub][ar1][o] = ra1h;
            *(uint4*)&s.Alo[buf][sub][ar1][o] = ra1l;
        }
        {
            int sub = bch >> 1, o = (bch & 1) * 8;
            *(uint4*)&s.Bhi[buf][sub][br][o] = rbh;
            *(uint4*)&s.Blo[buf][sub][br][o] = rbl;
        }
    };

    const int arow = lane & 15, acolB = (lane >> 4) * 16;      // bytes
    const int brow = lane & 7,  bcolB = ((lane >> 3) & 1) * 16;

    auto compute = [&](int buf) {
#pragma unroll
        for (int sub = 0; sub < 2; ++sub) {
            uint32_t aBaseH = smem_u32(&s.Ahi[buf][sub][0][0]);
            uint32_t aBaseL = smem_u32(&s.Alo[buf][sub][0][0]);
            uint32_t bBaseH = smem_u32(&s.Bhi[buf][sub][0][0]);
            uint32_t bBaseL = smem_u32(&s.Blo[buf][sub][0][0]);
            uint32_t ah[2][4], al[2][4], bh2[2][2], bl2[2][2];
#pragma unroll
            for (int fm = 0; fm < 2; ++fm) {
                int r = wm * 32 + fm * 16 + arow;
                ldm_x4(ah[fm], aBaseH + r * 48 + acolB);
                ldm_x4(al[fm], aBaseL + r * 48 + acolB);
            }
#pragma unroll
            for (int fn = 0; fn < 2; ++fn) {
                int r = wn * 16 + fn * 8 + brow;
                ldm_x2(bh2[fn], bBaseH + r * 48 + bcolB);
                ldm_x2(bl2[fn], bBaseL + r * 48 + bcolB);
            }
#pragma unroll
            for (int fm = 0; fm < 2; ++fm)
#pragma unroll
                for (int fn = 0; fn < 2; ++fn) {
                    mma_bf16(acc[fm][fn], ah[fm], bh2[fn]);
                    mma_bf16(acc[fm][fn], ah[fm], bl2[fn]);
                    mma_bf16(acc[fm][fn], al[fm], bh2[fn]);
                }
        }
    };

    gload(0);
    sstore(0);
    __syncthreads();
    for (int st = 0; st < 16; ++st) {
        if (st < 15) gload(st + 1);
        compute(st & 1);
        if (st < 15) sstore((st + 1) & 1);
        __syncthreads();
    }
}

// Epilogue iteration helper: maps acc to (row, col, value)
#define EPILOGUE_FOREACH(body)                                            \
    {                                                                     \
        const int lane = threadIdx.x & 31, wid = threadIdx.x >> 5;        \
        const int wm = wid & 1, wn = wid >> 1;                            \
        _Pragma("unroll") for (int fm = 0; fm < 2; ++fm)                  \
        _Pragma("unroll") for (int fn = 0; fn < 2; ++fn)                  \
        _Pragma("unroll") for (int h = 0; h < 2; ++h)                     \
        _Pragma("unroll") for (int e = 0; e < 2; ++e) {                   \
            int r = rowBase + wm * 32 + fm * 16 + (lane >> 2) + h * 8;    \
            int c = colBase + wn * 16 + fn * 8 + (lane & 3) * 2 + e;      \
            float v = acc[fm][fn][h * 2 + e];                             \
            body                                                          \
        }                                                                 \
    }

__device__ __forceinline__ void split_store(bf16* hi, bf16* lo, int off, float v) {
    bf16 h = __float2bfloat16(v);
    hi[off] = h;
    lo[off] = __float2bfloat16(v - __bfloat162float(h));
}

// ---------------------------------------------------------------------------
// Prep: split X, W2 into bf16 hi/lo; transpose+split W1->W1T, W2->W2T
// ---------------------------------------------------------------------------
__global__ void k_prep(const float* __restrict__ X, const float* __restrict__ W1,
                       const float* __restrict__ W2) {
    __shared__ float ts[32][33];
    const int task = blockIdx.y;
    const int tr = (blockIdx.x >> 4) * 32, tc = (blockIdx.x & 15) * 32;
    const int tx = threadIdx.x, ty = threadIdx.y;
    const float* src;
    bf16 *dhi, *dlo;
    bool trans;
    switch (task) {
        case 0:  src = X;  dhi = g_Xhi;   dlo = g_Xlo;   trans = false; break;
        case 1:  src = W1; dhi = g_W1Thi; dlo = g_W1Tlo; trans = true;  break;
        case 2:  src = W2; dhi = g_W2Thi; dlo = g_W2Tlo; trans = true;  break;
        default: src = W2; dhi = g_W2hi;  dlo = g_W2lo;  trans = false; break;
    }
    if (!trans) {
#pragma unroll
        for (int k = 0; k < 4; ++k) {
            int r = tr + ty + k * 8, c = tc + tx;
            split_store(dhi, dlo, r * NN + c, src[r * NN + c]);
        }
    } else {
#pragma unroll
        for (int k = 0; k < 4; ++k)
            ts[ty + k * 8][tx] = src[(tr + ty + k * 8) * NN + tc + tx];
        __syncthreads();
#pragma unroll
        for (int k = 0; k < 4; ++k) {
            int orow = tc + ty + k * 8, ocol = tr + tx;
            split_store(dhi, dlo, orow * NN + ocol, ts[tx][ty + k * 8]);
        }
    }
}

// ---------------------------------------------------------------------------
// GEMM kernels (grid: x = col tile of 32 (16), y = row tile of 64 (8))
// ---------------------------------------------------------------------------
__global__ void __launch_bounds__(128) k_fwd1(const float* __restrict__ b1) {
    __shared__ Smem s;
    const int rowBase = blockIdx.y * 64, colBase = blockIdx.x * 32;
    float acc[2][2][4] = {};
    mainloop(g_Xhi, g_Xlo, g_W1Thi, g_W1Tlo, rowBase, colBase, s, acc);
    EPILOGUE_FOREACH({
        float z = v + b1[c];
        float hv = fmaxf(z, 0.f);
        split_store(g_H1hi, g_H1lo, r * NN + c, hv);
    })
}

__global__ void __launch_bounds__(128) k_fwd2(const float* __restrict__ b2,
                                              const float* __restrict__ w3) {
    __shared__ Smem s;
    const int rowBase = blockIdx.y * 64, colBase = blockIdx.x * 32;
    float acc[2][2][4] = {};
    mainloop(g_H1hi, g_H1lo, g_W2Thi, g_W2Tlo, rowBase, colBase, s, acc);
    EPILOGUE_FOREACH({
        float z = v + b2[c];
        float hv = fmaxf(z, 0.f);
        int off = r * NN + c;
        g_H2f[off] = hv;
        split_store(g_H2hi, g_H2lo, off, hv);
        float g = (z > 0.f) ? w3[c] : 0.f;
        split_store(g_G2hi, g_G2lo, off, g);
    })
}

__global__ void __launch_bounds__(128) k_g1() {
    __shared__ Smem s;
    const int rowBase = blockIdx.y * 64, colBase = blockIdx.x * 32;
    float acc[2][2][4] = {};
    mainloop(g_G2hi, g_G2lo, g_W2hi, g_W2lo, rowBase, colBase, s, acc);
    EPILOGUE_FOREACH({
        int off = r * NN + c;
        float m = (__bfloat162float(g_H1hi[off]) > 0.f) ? v : 0.f;
        split_store(g_G1hi, g_G1lo, off, m);
    })
}

// Lower-triangle 64x32 block map: rb in [0,8), cb <= 2*rb+1; 72 blocks.
__device__ __forceinline__ void tri72(int L, int& rb, int& cb) {
    int r = 0, c = L;
    while (c >= 2 * r + 2) { c -= 2 * r + 2; ++r; }
    rb = r; cb = c;
}

__global__ void __launch_bounds__(128) k_gram() {
    __shared__ Smem s;
    int rb, cb;
    tri72(blockIdx.x, rb, cb);
    const bf16 *Ahi, *Alo;
    float* P;
    switch (blockIdx.y) {
        case 0:  Ahi = g_Xhi;  Alo = g_Xlo;  P = g_PX;  break;
        case 1:  Ahi = g_H1hi; Alo = g_H1lo; P = g_PH1; break;
        case 2:  Ahi = g_H2hi; Alo = g_H2lo; P = g_PH2; break;
        case 3:  Ahi = g_G1hi; Alo = g_G1lo; P = g_PG1; break;
        default: Ahi = g_G2hi; Alo = g_G2lo; P = g_PG2; break;
    }
    const int rowBase = rb * 64, colBase = cb * 32;
    float acc[2][2][4] = {};
    mainloop(Ahi, Alo, Ahi, Alo, rowBase, colBase, s, acc);
    EPILOGUE_FOREACH({ P[r * NN + c] = v; })
}

// ---------------------------------------------------------------------------
// out[i] = H2[i,:] . w3 + b3[0]   (one warp per row)
// ---------------------------------------------------------------------------
__global__ void __launch_bounds__(128) k_out(const float* __restrict__ w3,
                                             const float* __restrict__ b3,
                                             float* __restrict__ out) {
    const int w = threadIdx.x >> 5, lane = threadIdx.x & 31;
    const int row = blockIdx.x * 4 + w;
    const float4* h = (const float4*)(g_H2f + row * NN);
    const float4* wv = (const float4*)w3;
    float s = 0.f;
#pragma unroll
    for (int c = lane; c < NN / 4; c += 32) {
        float4 a = h[c], b = wv[c];
        s += a.x * b.x + a.y * b.y + a.z * b.z + a.w * b.w;
    }
#pragma unroll
    for (int o = 16; o > 0; o >>= 1) s += __shfl_xor_sync(0xffffffffu, s, o);
    if (lane == 0) out[row] = s + b3[0];
}

// ---------------------------------------------------------------------------
// Combine partials + mirror: Gram = 1 + sH2 + sG2*(1+sH1) + sG1*(1+sX)
// ---------------------------------------------------------------------------
__global__ void __launch_bounds__(256) k_combine(float* __restrict__ gram) {
    int rb, cb;
    tri72(blockIdx.x, rb, cb);
    const int rowBase = rb * 64, colBase = cb * 32;
    for (int idx = threadIdx.x; idx < 64 * 32; idx += 256) {
        int r = idx >> 5, c = idx & 31;
        int i = rowBase + r, j = colBase + c;
        if (j > i) continue;
        int off = i * NN + j;
        float g = 1.f + g_PH2[off] + g_PG2[off] * (1.f + g_PH1[off]) +
                  g_PG1[off] * (1.f + g_PX[off]);
        gram[off] = g;
        gram[j * NN + i] = g;
    }
}

// ---------------------------------------------------------------------------
// Launch
// ---------------------------------------------------------------------------
extern "C" void kernel_launch(void* const* d_in, const int* in_sizes, int n_in,
                              void* d_out, int out_size) {
    const float* x  = (const float*)d_in[0];
    const float* W1 = (const float*)d_in[1];
    const float* b1 = (const float*)d_in[2];
    const float* W2 = (const float*)d_in[3];
    const float* b2 = (const float*)d_in[4];
    const float* w3 = (const float*)d_in[5];
    const float* b3 = (const float*)d_in[6];

    float* out  = (float*)d_out;       // [512]
    float* gram = (float*)d_out + NN;  // [512 x 512]

    dim3 ggrid(16, 8);  // 128 CTAs
    k_prep<<<dim3(256, 4), dim3(32, 8)>>>(x, W1, W2);
    k_fwd1<<<ggrid, 128>>>(b1);
    k_fwd2<<<ggrid, 128>>>(b2, w3);
    k_g1<<<ggrid, 128>>>();
    k_out<<<128, 128>>>(w3, b3, out);
    k_gram<<<dim3(72, 5), 128>>>();
    k_combine<<<72, 256>>>(gram);
}

// round 5
// speedup vs baseline: 2.8794x; 1.0324x over previous
#include <cuda_runtime.h>
#include <cuda_bf16.h>
#include <cstdint>

#define NN 512
using bf16 = __nv_bfloat16;

// ---------------------------------------------------------------------------
// Device scratch (no allocation allowed)
// ---------------------------------------------------------------------------
#define DECLB(n) __device__ __align__(16) bf16 n[NN * NN]
DECLB(g_Xhi);   DECLB(g_Xlo);
DECLB(g_W1Thi); DECLB(g_W1Tlo);
DECLB(g_W2Thi); DECLB(g_W2Tlo);
DECLB(g_W2hi);  DECLB(g_W2lo);
DECLB(g_H1hi);  DECLB(g_H1lo);
DECLB(g_H2hi);  DECLB(g_H2lo);
DECLB(g_G1hi);  DECLB(g_G1lo);
DECLB(g_G2hi);  DECLB(g_G2lo);
__device__ __align__(16) float g_H2f[NN * NN];
__device__ __align__(16) float g_PX [NN * NN];
__device__ __align__(16) float g_PH1[NN * NN];
__device__ __align__(16) float g_PH2[NN * NN];
__device__ __align__(16) float g_PG1[NN * NN];
__device__ __align__(16) float g_PG2[NN * NN];

// ---------------------------------------------------------------------------
// PTX helpers (base PTX only — valid on virtual target sm_103)
// ---------------------------------------------------------------------------
__device__ __forceinline__ uint32_t smem_u32(const void* p) {
    return (uint32_t)__cvta_generic_to_shared(p);
}
__device__ __forceinline__ void ldm_x4(uint32_t a[4], uint32_t addr) {
    asm volatile("ldmatrix.sync.aligned.m8n8.x4.shared.b16 {%0,%1,%2,%3}, [%4];"
                 : "=r"(a[0]), "=r"(a[1]), "=r"(a[2]), "=r"(a[3]) : "r"(addr));
}
__device__ __forceinline__ void ldm_x2(uint32_t b[2], uint32_t addr) {
    asm volatile("ldmatrix.sync.aligned.m8n8.x2.shared.b16 {%0,%1}, [%2];"
                 : "=r"(b[0]), "=r"(b[1]) : "r"(addr));
}
__device__ __forceinline__ void mma_bf16(float c[4], const uint32_t a[4],
                                         const uint32_t b[2]) {
    asm volatile(
        "mma.sync.aligned.m16n8k16.row.col.f32.bf16.bf16.f32 "
        "{%0,%1,%2,%3}, {%4,%5,%6,%7}, {%8,%9}, {%0,%1,%2,%3};"
        : "+f"(c[0]), "+f"(c[1]), "+f"(c[2]), "+f"(c[3])
        : "r"(a[0]), "r"(a[1]), "r"(a[2]), "r"(a[3]), "r"(b[0]), "r"(b[1]));
}
__device__ __forceinline__ void cp16(uint32_t dst, const void* src) {
    asm volatile("cp.async.cg.shared.global [%0], [%1], 16;" :: "r"(dst), "l"(src));
}
#define CP_COMMIT() asm volatile("cp.async.commit_group;" ::: "memory")
#define CP_WAIT1()  asm volatile("cp.async.wait_group 1;" ::: "memory")

// ---------------------------------------------------------------------------
// SMEM ring layout (3 stages, k32/stage, 48B row stride).
// Stage layout (bytes): Ahi[2][64][24h]@0, Alo@6144, Bhi[2][32][24h]@12288,
// Blo@15360. Stage stride 18432 B. Total 3*18432 = 55296 B (dynamic).
// ---------------------------------------------------------------------------
constexpr int STAGE_B = 18432;
constexpr int A_LO_B  = 6144;
constexpr int B_HI_B  = 12288;
constexpr int B_LO_B  = 15360;
constexpr int SUB_A_B = 3072;   // 64 rows * 48 B
constexpr int SUB_B_B = 1536;   // 32 rows * 48 B
constexpr int SMEM_MAIN = 3 * STAGE_B;

// CTA tile M=64, N=32, 128 threads (4 warps: 2m x 2n; warp tile 32x16).
__device__ __forceinline__ void mainloop(
    const bf16* __restrict__ Ahi, const bf16* __restrict__ Alo,
    const bf16* __restrict__ Bhi, const bf16* __restrict__ Blo,
    int rowBase, int colBase, uint32_t sb, float acc[2][2][4])
{
    const int t = threadIdx.x;
    const int lane = t & 31, wid = t >> 5;
    const int wm = wid & 1, wn = wid >> 1;

    // cp.async task mapping: A = 256 16B-chunks (2/thread), B = 128 (1/thread)
    const int a0row = t >> 2,          a0c = t & 3;
    const int a1row = (t + 128) >> 2,  a1c = (t + 128) & 3;
    const int brow  = t >> 2,          bc  = t & 3;
    const uint32_t dA0 = (uint32_t)((a0c >> 1) * SUB_A_B + a0row * 48 + (a0c & 1) * 16);
    const uint32_t dA1 = (uint32_t)((a1c >> 1) * SUB_A_B + a1row * 48 + (a1c & 1) * 16);
    const uint32_t dB  = (uint32_t)((bc  >> 1) * SUB_B_B + brow * 48 + (bc  & 1) * 16);
    const bf16* pA0h = Ahi + (rowBase + a0row) * NN + a0c * 8;
    const bf16* pA0l = Alo + (rowBase + a0row) * NN + a0c * 8;
    const bf16* pA1h = Ahi + (rowBase + a1row) * NN + a1c * 8;
    const bf16* pA1l = Alo + (rowBase + a1row) * NN + a1c * 8;
    const bf16* pBh  = Bhi + (colBase + brow) * NN + bc * 8;
    const bf16* pBl  = Blo + (colBase + brow) * NN + bc * 8;

    auto issue = [&](int stg) {
        const uint32_t base = sb + (stg % 3) * STAGE_B;
        const int k0 = stg * 32;
        cp16(base + dA0,          pA0h + k0);
        cp16(base + A_LO_B + dA0, pA0l + k0);
        cp16(base + dA1,          pA1h + k0);
        cp16(base + A_LO_B + dA1, pA1l + k0);
        cp16(base + B_HI_B + dB,  pBh + k0);
        cp16(base + B_LO_B + dB,  pBl + k0);
        CP_COMMIT();
    };

    // ldmatrix per-warp offsets (bytes within a sub-slice)
    uint32_t aOff[2], bOff[2];
#pragma unroll
    for (int fm = 0; fm < 2; ++fm)
        aOff[fm] = (uint32_t)((wm * 32 + fm * 16 + (lane & 15)) * 48 + (lane >> 4) * 16);
#pragma unroll
    for (int fn = 0; fn < 2; ++fn)
        bOff[fn] = (uint32_t)((wn * 16 + fn * 8 + (lane & 7)) * 48 + ((lane >> 3) & 1) * 16);

    issue(0);
    issue(1);
    for (int st = 0; st < 16; ++st) {
        CP_WAIT1();
        __syncthreads();
        const uint32_t base = sb + (st % 3) * STAGE_B;
#pragma unroll
        for (int sub = 0; sub < 2; ++sub) {
            const uint32_t aH = base + sub * SUB_A_B;
            const uint32_t aL = aH + A_LO_B;
            const uint32_t bH = base + B_HI_B + sub * SUB_B_B;
            const uint32_t bL = base + B_LO_B + sub * SUB_B_B;
            uint32_t ah[2][4], al[2][4], bh2[2][2], bl2[2][2];
#pragma unroll
            for (int fm = 0; fm < 2; ++fm) {
                ldm_x4(ah[fm], aH + aOff[fm]);
                ldm_x4(al[fm], aL + aOff[fm]);
            }
#pragma unroll
            for (int fn = 0; fn < 2; ++fn) {
                ldm_x2(bh2[fn], bH + bOff[fn]);
                ldm_x2(bl2[fn], bL + bOff[fn]);
            }
#pragma unroll
            for (int fm = 0; fm < 2; ++fm)
#pragma unroll
                for (int fn = 0; fn < 2; ++fn) {
                    mma_bf16(acc[fm][fn], ah[fm], bh2[fn]);
                    mma_bf16(acc[fm][fn], ah[fm], bl2[fn]);
                    mma_bf16(acc[fm][fn], al[fm], bh2[fn]);
                }
        }
        if (st < 14) issue(st + 2);
        else CP_COMMIT();
    }
}

// Epilogue iteration helper: maps acc to (row, col, value)
#define EPILOGUE_FOREACH(body)                                            \
    {                                                                     \
        const int lane = threadIdx.x & 31, wid = threadIdx.x >> 5;        \
        const int wm = wid & 1, wn = wid >> 1;                            \
        _Pragma("unroll") for (int fm = 0; fm < 2; ++fm)                  \
        _Pragma("unroll") for (int fn = 0; fn < 2; ++fn)                  \
        _Pragma("unroll") for (int h = 0; h < 2; ++h)                     \
        _Pragma("unroll") for (int e = 0; e < 2; ++e) {                   \
            int r = rowBase + wm * 32 + fm * 16 + (lane >> 2) + h * 8;    \
            int c = colBase + wn * 16 + fn * 8 + (lane & 3) * 2 + e;      \
            float v = acc[fm][fn][h * 2 + e];                             \
            body                                                          \
        }                                                                 \
    }

__device__ __forceinline__ void split_store(bf16* hi, bf16* lo, int off, float v) {
    bf16 h = __float2bfloat16(v);
    hi[off] = h;
    lo[off] = __float2bfloat16(v - __bfloat162float(h));
}

// ---------------------------------------------------------------------------
// Prep: split X, W2 into bf16 hi/lo; transpose+split W1->W1T, W2->W2T
// ---------------------------------------------------------------------------
__global__ void k_prep(const float* __restrict__ X, const float* __restrict__ W1,
                       const float* __restrict__ W2) {
    __shared__ float ts[32][33];
    const int task = blockIdx.y;
    const int tr = (blockIdx.x >> 4) * 32, tc = (blockIdx.x & 15) * 32;
    const int tx = threadIdx.x, ty = threadIdx.y;
    const float* src;
    bf16 *dhi, *dlo;
    bool trans;
    switch (task) {
        case 0:  src = X;  dhi = g_Xhi;   dlo = g_Xlo;   trans = false; break;
        case 1:  src = W1; dhi = g_W1Thi; dlo = g_W1Tlo; trans = true;  break;
        case 2:  src = W2; dhi = g_W2Thi; dlo = g_W2Tlo; trans = true;  break;
        default: src = W2; dhi = g_W2hi;  dlo = g_W2lo;  trans = false; break;
    }
    if (!trans) {
#pragma unroll
        for (int k = 0; k < 4; ++k) {
            int r = tr + ty + k * 8, c = tc + tx;
            split_store(dhi, dlo, r * NN + c, src[r * NN + c]);
        }
    } else {
#pragma unroll
        for (int k = 0; k < 4; ++k)
            ts[ty + k * 8][tx] = src[(tr + ty + k * 8) * NN + tc + tx];
        __syncthreads();
#pragma unroll
        for (int k = 0; k < 4; ++k) {
            int orow = tc + ty + k * 8, ocol = tr + tx;
            split_store(dhi, dlo, orow * NN + ocol, ts[tx][ty + k * 8]);
        }
    }
}

// ---------------------------------------------------------------------------
// GEMM kernels (grid: x = col tile of 32 (16), y = row tile of 64 (8))
// ---------------------------------------------------------------------------
__global__ void __launch_bounds__(128) k_fwd1(const float* __restrict__ b1) {
    extern __shared__ char dsm[];
    const uint32_t sb = smem_u32(dsm);
    const int rowBase = blockIdx.y * 64, colBase = blockIdx.x * 32;
    float acc[2][2][4] = {};
    mainloop(g_Xhi, g_Xlo, g_W1Thi, g_W1Tlo, rowBase, colBase, sb, acc);
    EPILOGUE_FOREACH({
        float z = v + b1[c];
        float hv = fmaxf(z, 0.f);
        split_store(g_H1hi, g_H1lo, r * NN + c, hv);
    })
}

__global__ void __launch_bounds__(128) k_fwd2(const float* __restrict__ b2,
                                              const float* __restrict__ w3) {
    extern __shared__ char dsm[];
    const uint32_t sb = smem_u32(dsm);
    const int rowBase = blockIdx.y * 64, colBase = blockIdx.x * 32;
    float acc[2][2][4] = {};
    mainloop(g_H1hi, g_H1lo, g_W2Thi, g_W2Tlo, rowBase, colBase, sb, acc);
    EPILOGUE_FOREACH({
        float z = v + b2[c];
        float hv = fmaxf(z, 0.f);
        int off = r * NN + c;
        g_H2f[off] = hv;
        split_store(g_H2hi, g_H2lo, off, hv);
        float g = (z > 0.f) ? w3[c] : 0.f;
        split_store(g_G2hi, g_G2lo, off, g);
    })
}

__global__ void __launch_bounds__(128) k_g1() {
    extern __shared__ char dsm[];
    const uint32_t sb = smem_u32(dsm);
    const int rowBase = blockIdx.y * 64, colBase = blockIdx.x * 32;
    float acc[2][2][4] = {};
    mainloop(g_G2hi, g_G2lo, g_W2hi, g_W2lo, rowBase, colBase, sb, acc);
    EPILOGUE_FOREACH({
        int off = r * NN + c;
        float m = (__bfloat162float(g_H1hi[off]) > 0.f) ? v : 0.f;
        split_store(g_G1hi, g_G1lo, off, m);
    })
}

// Lower-triangle 64x32 block map: rb in [0,8), cb <= 2*rb+1; 72 blocks.
__device__ __forceinline__ void tri72(int L, int& rb, int& cb) {
    int r = 0, c = L;
    while (c >= 2 * r + 2) { c -= 2 * r + 2; ++r; }
    rb = r; cb = c;
}

__global__ void __launch_bounds__(128) k_gram() {
    extern __shared__ char dsm[];
    const uint32_t sb = smem_u32(dsm);
    int rb, cb;
    tri72(blockIdx.x, rb, cb);
    const bf16 *Ahi, *Alo;
    float* P;
    switch (blockIdx.y) {
        case 0:  Ahi = g_Xhi;  Alo = g_Xlo;  P = g_PX;  break;
        case 1:  Ahi = g_H1hi; Alo = g_H1lo; P = g_PH1; break;
        case 2:  Ahi = g_H2hi; Alo = g_H2lo; P = g_PH2; break;
        case 3:  Ahi = g_G1hi; Alo = g_G1lo; P = g_PG1; break;
        default: Ahi = g_G2hi; Alo = g_G2lo; P = g_PG2; break;
    }
    const int rowBase = rb * 64, colBase = cb * 32;
    float acc[2][2][4] = {};
    mainloop(Ahi, Alo, Ahi, Alo, rowBase, colBase, sb, acc);
    EPILOGUE_FOREACH({ P[r * NN + c] = v; })
}

// ---------------------------------------------------------------------------
// out[i] = H2[i,:] . w3 + b3[0]   (one warp per row)
// ---------------------------------------------------------------------------
__global__ void __launch_bounds__(128) k_out(const float* __restrict__ w3,
                                             const float* __restrict__ b3,
                                             float* __restrict__ out) {
    const int w = threadIdx.x >> 5, lane = threadIdx.x & 31;
    const int row = blockIdx.x * 4 + w;
    const float4* h = (const float4*)(g_H2f + row * NN);
    const float4* wv = (const float4*)w3;
    float s = 0.f;
#pragma unroll
    for (int c = lane; c < NN / 4; c += 32) {
        float4 a = h[c], b = wv[c];
        s += a.x * b.x + a.y * b.y + a.z * b.z + a.w * b.w;
    }
#pragma unroll
    for (int o = 16; o > 0; o >>= 1) s += __shfl_xor_sync(0xffffffffu, s, o);
    if (lane == 0) out[row] = s + b3[0];
}

// ---------------------------------------------------------------------------
// Combine partials + mirror: Gram = 1 + sH2 + sG2*(1+sH1) + sG1*(1+sX)
// ---------------------------------------------------------------------------
__global__ void __launch_bounds__(256) k_combine(float* __restrict__ gram) {
    int rb, cb;
    tri72(blockIdx.x, rb, cb);
    const int rowBase = rb * 64, colBase = cb * 32;
    for (int idx = threadIdx.x; idx < 64 * 32; idx += 256) {
        int r = idx >> 5, c = idx & 31;
        int i = rowBase + r, j = colBase + c;
        if (j > i) continue;
        int off = i * NN + j;
        float g = 1.f + g_PH2[off] + g_PG2[off] * (1.f + g_PH1[off]) +
                  g_PG1[off] * (1.f + g_PX[off]);
        gram[off] = g;
        gram[j * NN + i] = g;
    }
}

// ---------------------------------------------------------------------------
// Launch
// ---------------------------------------------------------------------------
extern "C" void kernel_launch(void* const* d_in, const int* in_sizes, int n_in,
                              void* d_out, int out_size) {
    const float* x  = (const float*)d_in[0];
    const float* W1 = (const float*)d_in[1];
    const float* b1 = (const float*)d_in[2];
    const float* W2 = (const float*)d_in[3];
    const float* b2 = (const float*)d_in[4];
    const float* w3 = (const float*)d_in[5];
    const float* b3 = (const float*)d_in[6];

    float* out  = (float*)d_out;       // [512]
    float* gram = (float*)d_out + NN;  // [512 x 512]

    cudaFuncSetAttribute(k_fwd1, cudaFuncAttributeMaxDynamicSharedMemorySize, SMEM_MAIN);
    cudaFuncSetAttribute(k_fwd2, cudaFuncAttributeMaxDynamicSharedMemorySize, SMEM_MAIN);
    cudaFuncSetAttribute(k_g1,   cudaFuncAttributeMaxDynamicSharedMemorySize, SMEM_MAIN);
    cudaFuncSetAttribute(k_gram, cudaFuncAttributeMaxDynamicSharedMemorySize, SMEM_MAIN);

    dim3 ggrid(16, 8);  // 128 CTAs
    k_prep<<<dim3(256, 4), dim3(32, 8)>>>(x, W1, W2);
    k_fwd1<<<ggrid, 128, SMEM_MAIN>>>(b1);
    k_fwd2<<<ggrid, 128, SMEM_MAIN>>>(b2, w3);
    k_g1<<<ggrid, 128, SMEM_MAIN>>>();
    k_out<<<128, 128>>>(w3, b3, out);
    k_gram<<<dim3(72, 5), 128, SMEM_MAIN>>>();
    k_combine<<<72, 256>>>(gram);
}

// round 6
// speedup vs baseline: 2.9712x; 1.0319x over previous
#include <cuda_runtime.h>
#include <cuda_bf16.h>
#include <cstdint>

#define NN 512
using bf16 = __nv_bfloat16;

// ---------------------------------------------------------------------------
// Device scratch (no allocation allowed)
// ---------------------------------------------------------------------------
#define DECLB(n) __device__ __align__(16) bf16 n[NN * NN]
DECLB(g_Xhi);   DECLB(g_Xlo);
DECLB(g_W1Thi); DECLB(g_W1Tlo);
DECLB(g_W2Thi); DECLB(g_W2Tlo);
DECLB(g_W2hi);  DECLB(g_W2lo);
DECLB(g_H1hi);  DECLB(g_H1lo);
DECLB(g_H2hi);  DECLB(g_H2lo);
DECLB(g_G1hi);  DECLB(g_G1lo);
DECLB(g_G2hi);  DECLB(g_G2lo);
__device__ __align__(16) float g_H2f[NN * NN];
__device__ __align__(16) float g_PX [NN * NN];
__device__ __align__(16) float g_PH1[NN * NN];
__device__ __align__(16) float g_PH2[NN * NN];
__device__ __align__(16) float g_PG1[NN * NN];
__device__ __align__(16) float g_PG2[NN * NN];

// ---------------------------------------------------------------------------
// PTX helpers (base PTX only — valid on virtual target sm_103)
// ---------------------------------------------------------------------------
__device__ __forceinline__ uint32_t smem_u32(const void* p) {
    return (uint32_t)__cvta_generic_to_shared(p);
}
__device__ __forceinline__ void ldm_x4(uint32_t a[4], uint32_t addr) {
    asm volatile("ldmatrix.sync.aligned.m8n8.x4.shared.b16 {%0,%1,%2,%3}, [%4];"
                 : "=r"(a[0]), "=r"(a[1]), "=r"(a[2]), "=r"(a[3]) : "r"(addr));
}
__device__ __forceinline__ void mma_bf16(float c[4], const uint32_t a[4],
                                         const uint32_t b[2]) {
    asm volatile(
        "mma.sync.aligned.m16n8k16.row.col.f32.bf16.bf16.f32 "
        "{%0,%1,%2,%3}, {%4,%5,%6,%7}, {%8,%9}, {%0,%1,%2,%3};"
        : "+f"(c[0]), "+f"(c[1]), "+f"(c[2]), "+f"(c[3])
        : "r"(a[0]), "r"(a[1]), "r"(a[2]), "r"(a[3]), "r"(b[0]), "r"(b[1]));
}
__device__ __forceinline__ void cp16(uint32_t dst, const void* src) {
    asm volatile("cp.async.cg.shared.global [%0], [%1], 16;" :: "r"(dst), "l"(src));
}
#define CP_COMMIT() asm volatile("cp.async.commit_group;" ::: "memory")
#define CP_WAIT2()  asm volatile("cp.async.wait_group 2;" ::: "memory")

// ---------------------------------------------------------------------------
// SMEM ring: 4 stages, k32/stage (2 k16 sub-slices), 48B row stride.
// Stage layout (bytes): Ahi[2][64][24h]@0, Alo@6144, Bhi[2][32][24h]@12288,
// Blo@15360. Stage stride 18432 B. Total 4*18432 = 73728 B (dynamic smem).
// ---------------------------------------------------------------------------
constexpr int SUB_A_B = 3072;   // 64 rows * 48 B
constexpr int SUB_B_B = 1536;   // 32 rows * 48 B
constexpr int A_LO_B  = 6144;
constexpr int B_HI_B  = 12288;
constexpr int B_LO_B  = 15360;
constexpr int STAGE_B = 18432;
constexpr int SMEM_MAIN = 4 * STAGE_B;

// CTA tile M=64, N=32, 256 threads (8 warps: 4m x 2n; warp tile 16x16).
// acc[fn][4]: two m16n8 fragments per warp.
__device__ __forceinline__ void mainloop(
    const bf16* __restrict__ Ahi, const bf16* __restrict__ Alo,
    const bf16* __restrict__ Bhi, const bf16* __restrict__ Blo,
    int rowBase, int colBase, uint32_t sb, float acc[2][4])
{
    const int t = threadIdx.x;
    const int lane = t & 31, wid = t >> 5;
    const int wm = wid & 3, wn = wid >> 2;

    // cp.async mapping: 3 chunks of 16B per thread (A-hi, A-lo, one B chunk)
    const int arow = t >> 2, ac = t & 3;
    const uint32_t dA = (uint32_t)((ac >> 1) * SUB_A_B + arow * 48 + (ac & 1) * 16);
    const int u = t & 127;
    const int brow = u >> 2, bc = u & 3;
    const uint32_t dB = (uint32_t)((t < 128 ? B_HI_B : B_LO_B) +
                                   (bc >> 1) * SUB_B_B + brow * 48 + (bc & 1) * 16);
    const bf16* pAh = Ahi + (rowBase + arow) * NN + ac * 8;
    const bf16* pAl = Alo + (rowBase + arow) * NN + ac * 8;
    const bf16* pB  = (t < 128 ? Bhi : Blo) + (colBase + brow) * NN + bc * 8;

    auto issue = [&](int stg) {
        const uint32_t base = sb + (stg & 3) * STAGE_B;
        const int k0 = stg * 32;
        cp16(base + dA,          pAh + k0);
        cp16(base + A_LO_B + dA, pAl + k0);
        cp16(base + dB,          pB + k0);
        CP_COMMIT();
    };

    // ldmatrix offsets (bytes within a sub-slice)
    const uint32_t aOff =
        (uint32_t)((wm * 16 + (lane & 15)) * 48 + (lane >> 4) * 16);
    const uint32_t bOff =
        (uint32_t)((wn * 16 + (lane & 7) + ((lane >> 4) & 1) * 8) * 48 +
                   ((lane >> 3) & 1) * 16);

    issue(0); issue(1); issue(2);
    for (int st = 0; st < 16; ++st) {
        CP_WAIT2();
        __syncthreads();
        const uint32_t base = sb + (st & 3) * STAGE_B;
#pragma unroll
        for (int sub = 0; sub < 2; ++sub) {
            uint32_t ah[4], al[4], bh[4], bl[4];
            ldm_x4(ah, base + sub * SUB_A_B + aOff);
            ldm_x4(al, base + A_LO_B + sub * SUB_A_B + aOff);
            ldm_x4(bh, base + B_HI_B + sub * SUB_B_B + bOff);
            ldm_x4(bl, base + B_LO_B + sub * SUB_B_B + bOff);
#pragma unroll
            for (int fn = 0; fn < 2; ++fn) {
                mma_bf16(acc[fn], ah, bh + 2 * fn);
                mma_bf16(acc[fn], ah, bl + 2 * fn);
                mma_bf16(acc[fn], al, bh + 2 * fn);
            }
        }
        if (st < 13) issue(st + 3);
        else CP_COMMIT();
    }
}

// Epilogue iteration helper: maps acc[2][4] to (row, col, value)
#define EPILOGUE_FOREACH(body)                                            \
    {                                                                     \
        const int lane = threadIdx.x & 31, wid = threadIdx.x >> 5;        \
        const int wm = wid & 3, wn = wid >> 2;                            \
        _Pragma("unroll") for (int fn = 0; fn < 2; ++fn)                  \
        _Pragma("unroll") for (int h = 0; h < 2; ++h)                     \
        _Pragma("unroll") for (int e = 0; e < 2; ++e) {                   \
            int r = rowBase + wm * 16 + (lane >> 2) + h * 8;              \
            int c = colBase + wn * 16 + fn * 8 + (lane & 3) * 2 + e;      \
            float v = acc[fn][h * 2 + e];                                 \
            body                                                          \
        }                                                                 \
    }

__device__ __forceinline__ void split_store(bf16* hi, bf16* lo, int off, float v) {
    bf16 h = __float2bfloat16(v);
    hi[off] = h;
    lo[off] = __float2bfloat16(v - __bfloat162float(h));
}

// ---------------------------------------------------------------------------
// Prep: split X, W2 into bf16 hi/lo; transpose+split W1->W1T, W2->W2T
// ---------------------------------------------------------------------------
__global__ void k_prep(const float* __restrict__ X, const float* __restrict__ W1,
                       const float* __restrict__ W2) {
    __shared__ float ts[32][33];
    const int task = blockIdx.y;
    const int tr = (blockIdx.x >> 4) * 32, tc = (blockIdx.x & 15) * 32;
    const int tx = threadIdx.x, ty = threadIdx.y;
    const float* src;
    bf16 *dhi, *dlo;
    bool trans;
    switch (task) {
        case 0:  src = X;  dhi = g_Xhi;   dlo = g_Xlo;   trans = false; break;
        case 1:  src = W1; dhi = g_W1Thi; dlo = g_W1Tlo; trans = true;  break;
        case 2:  src = W2; dhi = g_W2Thi; dlo = g_W2Tlo; trans = true;  break;
        default: src = W2; dhi = g_W2hi;  dlo = g_W2lo;  trans = false; break;
    }
    if (!trans) {
#pragma unroll
        for (int k = 0; k < 4; ++k) {
            int r = tr + ty + k * 8, c = tc + tx;
            split_store(dhi, dlo, r * NN + c, src[r * NN + c]);
        }
    } else {
#pragma unroll
        for (int k = 0; k < 4; ++k)
            ts[ty + k * 8][tx] = src[(tr + ty + k * 8) * NN + tc + tx];
        __syncthreads();
#pragma unroll
        for (int k = 0; k < 4; ++k) {
            int orow = tc + ty + k * 8, ocol = tr + tx;
            split_store(dhi, dlo, orow * NN + ocol, ts[tx][ty + k * 8]);
        }
    }
}

// ---------------------------------------------------------------------------
// GEMM kernels (grid: x = col tile of 32 (16), y = row tile of 64 (8))
// ---------------------------------------------------------------------------
__global__ void __launch_bounds__(256) k_fwd1(const float* __restrict__ b1) {
    extern __shared__ char dsm[];
    const uint32_t sb = smem_u32(dsm);
    const int rowBase = blockIdx.y * 64, colBase = blockIdx.x * 32;
    float acc[2][4] = {};
    mainloop(g_Xhi, g_Xlo, g_W1Thi, g_W1Tlo, rowBase, colBase, sb, acc);
    EPILOGUE_FOREACH({
        float z = v + b1[c];
        float hv = fmaxf(z, 0.f);
        split_store(g_H1hi, g_H1lo, r * NN + c, hv);
    })
}

__global__ void __launch_bounds__(256) k_fwd2(const float* __restrict__ b2,
                                              const float* __restrict__ w3) {
    extern __shared__ char dsm[];
    const uint32_t sb = smem_u32(dsm);
    const int rowBase = blockIdx.y * 64, colBase = blockIdx.x * 32;
    float acc[2][4] = {};
    mainloop(g_H1hi, g_H1lo, g_W2Thi, g_W2Tlo, rowBase, colBase, sb, acc);
    EPILOGUE_FOREACH({
        float z = v + b2[c];
        float hv = fmaxf(z, 0.f);
        int off = r * NN + c;
        g_H2f[off] = hv;
        split_store(g_H2hi, g_H2lo, off, hv);
        float g = (z > 0.f) ? w3[c] : 0.f;
        split_store(g_G2hi, g_G2lo, off, g);
    })
}

__global__ void __launch_bounds__(256) k_g1() {
    extern __shared__ char dsm[];
    const uint32_t sb = smem_u32(dsm);
    const int rowBase = blockIdx.y * 64, colBase = blockIdx.x * 32;
    float acc[2][4] = {};
    mainloop(g_G2hi, g_G2lo, g_W2hi, g_W2lo, rowBase, colBase, sb, acc);
    EPILOGUE_FOREACH({
        int off = r * NN + c;
        float m = (__bfloat162float(g_H1hi[off]) > 0.f) ? v : 0.f;
        split_store(g_G1hi, g_G1lo, off, m);
    })
}

// Lower-triangle 64x32 block map: rb in [0,8), cb <= 2*rb+1; 72 blocks.
__device__ __forceinline__ void tri72(int L, int& rb, int& cb) {
    int r = 0, c = L;
    while (c >= 2 * r + 2) { c -= 2 * r + 2; ++r; }
    rb = r; cb = c;
}

__global__ void __launch_bounds__(256) k_gram() {
    extern __shared__ char dsm[];
    const uint32_t sb = smem_u32(dsm);
    int rb, cb;
    tri72(blockIdx.x, rb, cb);
    const bf16 *Ahi, *Alo;
    float* P;
    switch (blockIdx.y) {
        case 0:  Ahi = g_Xhi;  Alo = g_Xlo;  P = g_PX;  break;
        case 1:  Ahi = g_H1hi; Alo = g_H1lo; P = g_PH1; break;
        case 2:  Ahi = g_H2hi; Alo = g_H2lo; P = g_PH2; break;
        case 3:  Ahi = g_G1hi; Alo = g_G1lo; P = g_PG1; break;
        default: Ahi = g_G2hi; Alo = g_G2lo; P = g_PG2; break;
    }
    const int rowBase = rb * 64, colBase = cb * 32;
    float acc[2][4] = {};
    mainloop(Ahi, Alo, Ahi, Alo, rowBase, colBase, sb, acc);
    EPILOGUE_FOREACH({ P[r * NN + c] = v; })
}

// ---------------------------------------------------------------------------
// out[i] = H2[i,:] . w3 + b3[0]   (one warp per row)
// ---------------------------------------------------------------------------
__global__ void __launch_bounds__(128) k_out(const float* __restrict__ w3,
                                             const float* __restrict__ b3,
                                             float* __restrict__ out) {
    const int w = threadIdx.x >> 5, lane = threadIdx.x & 31;
    const int row = blockIdx.x * 4 + w;
    const float4* h = (const float4*)(g_H2f + row * NN);
    const float4* wv = (const float4*)w3;
    float s = 0.f;
#pragma unroll
    for (int c = lane; c < NN / 4; c += 32) {
        float4 a = h[c], b = wv[c];
        s += a.x * b.x + a.y * b.y + a.z * b.z + a.w * b.w;
    }
#pragma unroll
    for (int o = 16; o > 0; o >>= 1) s += __shfl_xor_sync(0xffffffffu, s, o);
    if (lane == 0) out[row] = s + b3[0];
}

// ---------------------------------------------------------------------------
// Combine partials + mirror: Gram = 1 + sH2 + sG2*(1+sH1) + sG1*(1+sX)
// ---------------------------------------------------------------------------
__global__ void __launch_bounds__(256) k_combine(float* __restrict__ gram) {
    int rb, cb;
    tri72(blockIdx.x, rb, cb);
    const int rowBase = rb * 64, colBase = cb * 32;
    for (int idx = threadIdx.x; idx < 64 * 32; idx += 256) {
        int r = idx >> 5, c = idx & 31;
        int i = rowBase + r, j = colBase + c;
        if (j > i) continue;
        int off = i * NN + j;
        float g = 1.f + g_PH2[off] + g_PG2[off] * (1.f + g_PH1[off]) +
                  g_PG1[off] * (1.f + g_PX[off]);
        gram[off] = g;
        gram[j * NN + i] = g;
    }
}

// ---------------------------------------------------------------------------
// Launch
// ---------------------------------------------------------------------------
extern "C" void kernel_launch(void* const* d_in, const int* in_sizes, int n_in,
                              void* d_out, int out_size) {
    const float* x  = (const float*)d_in[0];
    const float* W1 = (const float*)d_in[1];
    const float* b1 = (const float*)d_in[2];
    const float* W2 = (const float*)d_in[3];
    const float* b2 = (const float*)d_in[4];
    const float* w3 = (const float*)d_in[5];
    const float* b3 = (const float*)d_in[6];

    float* out  = (float*)d_out;       // [512]
    float* gram = (float*)d_out + NN;  // [512 x 512]

    cudaFuncSetAttribute(k_fwd1, cudaFuncAttributeMaxDynamicSharedMemorySize, SMEM_MAIN);
    cudaFuncSetAttribute(k_fwd2, cudaFuncAttributeMaxDynamicSharedMemorySize, SMEM_MAIN);
    cudaFuncSetAttribute(k_g1,   cudaFuncAttributeMaxDynamicSharedMemorySize, SMEM_MAIN);
    cudaFuncSetAttribute(k_gram, cudaFuncAttributeMaxDynamicSharedMemorySize, SMEM_MAIN);

    dim3 ggrid(16, 8);  // 128 CTAs
    k_prep<<<dim3(256, 4), dim3(32, 8)>>>(x, W1, W2);
    k_fwd1<<<ggrid, 256, SMEM_MAIN>>>(b1);
    k_fwd2<<<ggrid, 256, SMEM_MAIN>>>(b2, w3);
    k_g1<<<ggrid, 256, SMEM_MAIN>>>();
    k_out<<<128, 128>>>(w3, b3, out);
    k_gram<<<dim3(72, 5), 256, SMEM_MAIN>>>();
    k_combine<<<72, 256>>>(gram);
}